// round 11
// baseline (speedup 1.0000x reference)
#include <cuda_runtime.h>
#include <cuda_fp16.h>
#include <math.h>
#include <stdint.h>

// Problem constants (B=2, T=2048, C=1024, H=16, D=64)
#define B_  2
#define T_  2048
#define C_  1024
#define H_  16
#define D_  64
#define M_  (B_*T_)        // 4096 rows
#define N3  (3*C_)         // 3072

// Scratch
__device__ __half g_xh  [M_*C_];
__device__ __half g_qkv [M_*N3];     // [row][3072]: q | k | v
__device__ __half g_yh  [M_*C_];
__device__ __half g_wcat[N3*C_];     // transposed [n][k], q|k|v stacked
__device__ __half g_wpt [C_*C_];

// ----------------------------------------------------------------------------
// Helpers
// ----------------------------------------------------------------------------
__device__ __forceinline__ void mma_f16(float* c, const uint32_t* a,
                                        uint32_t b0, uint32_t b1) {
    asm volatile(
        "mma.sync.aligned.m16n8k16.row.col.f32.f16.f16.f32 "
        "{%0,%1,%2,%3}, {%4,%5,%6,%7}, {%8,%9}, {%0,%1,%2,%3};"
        : "+f"(c[0]), "+f"(c[1]), "+f"(c[2]), "+f"(c[3])
        : "r"(a[0]), "r"(a[1]), "r"(a[2]), "r"(a[3]), "r"(b0), "r"(b1));
}

__device__ __forceinline__ void cpasync16(void* s, const void* g) {
    uint32_t sp = (uint32_t)__cvta_generic_to_shared(s);
    asm volatile("cp.async.cg.shared.global [%0], [%1], 16;" :: "r"(sp), "l"(g));
}
#define CP_COMMIT() asm volatile("cp.async.commit_group;" ::: "memory")
template <int N> __device__ __forceinline__ void cp_wait() {
    asm volatile("cp.async.wait_group %0;" :: "n"(N) : "memory");
}

__device__ __forceinline__ void ldsm_x4(uint32_t& r0, uint32_t& r1,
                                        uint32_t& r2, uint32_t& r3,
                                        uint32_t saddr) {
    asm volatile(
        "ldmatrix.sync.aligned.m8n8.x4.shared.b16 {%0,%1,%2,%3}, [%4];"
        : "=r"(r0), "=r"(r1), "=r"(r2), "=r"(r3) : "r"(saddr));
}
__device__ __forceinline__ void ldsm_x4_t(uint32_t& r0, uint32_t& r1,
                                          uint32_t& r2, uint32_t& r3,
                                          uint32_t saddr) {
    asm volatile(
        "ldmatrix.sync.aligned.m8n8.x4.trans.shared.b16 {%0,%1,%2,%3}, [%4];"
        : "=r"(r0), "=r"(r1), "=r"(r2), "=r"(r3) : "r"(saddr));
}

__device__ __forceinline__ float ex2f(float x) {
    float y;
    asm("ex2.approx.ftz.f32 %0, %1;" : "=f"(y) : "f"(x));
    return y;
}

__device__ __forceinline__ uint32_t packh2(float a, float b) {
    __half2 h = __floats2half2_rn(a, b);
    return *(uint32_t*)&h;
}

// ----------------------------------------------------------------------------
// Pre-pass: x -> half ; all 4 weights -> half transposed [n][k] (one kernel)
// ----------------------------------------------------------------------------
__global__ __launch_bounds__(256) void conv_xh(
    const float* __restrict__ in, __half* __restrict__ outp)
{
    const int i = blockIdx.x * 256 + threadIdx.x;
    float4 v = ((const float4*)in)[i];
    __half2 h0 = __floats2half2_rn(v.x, v.y);
    __half2 h1 = __floats2half2_rn(v.z, v.w);
    ((uint2*)outp)[i] = make_uint2(*(uint32_t*)&h0, *(uint32_t*)&h1);
}

__global__ __launch_bounds__(256) void trans_all(
    const float* __restrict__ Wq, const float* __restrict__ Wk,
    const float* __restrict__ Wv, const float* __restrict__ Wp,
    __half* __restrict__ wcat, __half* __restrict__ wpt)
{
    __shared__ float t[32][33];
    const int z = blockIdx.z;
    const float* W = (z == 0) ? Wq : (z == 1) ? Wk : (z == 2) ? Wv : Wp;
    __half* Wt = (z < 3) ? (wcat + (size_t)z * C_ * C_) : wpt;

    const int tx = threadIdx.x & 31;
    const int ty = threadIdx.x >> 5;
    const int bx = blockIdx.x * 32;       // n block
    const int by = blockIdx.y * 32;       // k block
    #pragma unroll
    for (int i = ty; i < 32; i += 8)
        t[i][tx] = W[(size_t)(by + i) * C_ + bx + tx];
    __syncthreads();
    #pragma unroll
    for (int i = ty; i < 32; i += 8)
        Wt[(size_t)(bx + i) * C_ + by + tx] = __float2half(t[tx][i]);
}

// ----------------------------------------------------------------------------
// FP16 GEMM, ldmatrix fragments. D[m][n] = sum_k A[m][k]*Bt[n][k].
// MODE 1: N=3072, half out stride 3072, fused RoPE+RMSNorm on cols<2048.
// MODE 0: N=1024, fp32 out stride 1024.
// ----------------------------------------------------------------------------
#define GBM 128
#define GBN 128
#define GBK 64
#define GSTR 72
#define GNKT (C_/GBK)                         // 16
#define GSTAGE ((GBM + GBN) * GSTR)           // halfs per stage
#define GEMM_SMEM (2 * GSTAGE * 2)            // 73728 B

template<int MODE>
__global__ __launch_bounds__(256, 2) void gemm2(
    const __half* __restrict__ A, const __half* __restrict__ Bt, void* Co,
    const float* __restrict__ cosb, const float* __restrict__ sinb)
{
    extern __shared__ __half hsm[];
    constexpr int OSTR = MODE ? N3 : C_;

    const int tid  = threadIdx.x;
    const int lane = tid & 31;
    const int wid  = tid >> 5;
    const int wm   = wid >> 1;       // 0..3
    const int wn   = wid & 1;        // 0..1
    const int bm = blockIdx.y * GBM;
    const int bn = blockIdx.x * GBN;
    const int r  = lane >> 2;        // 0..7
    const int cq = lane & 3;         // 0..3

    const int lm_off = ((((lane >> 3) & 1) * 8 + (lane & 7)) * GSTR
                        + (lane >> 4) * 8) * 2;   // bytes

    float acc[2][8][4];
    #pragma unroll
    for (int mt = 0; mt < 2; mt++)
        #pragma unroll
        for (int nt = 0; nt < 8; nt++)
            #pragma unroll
            for (int i = 0; i < 4; i++) acc[mt][nt][i] = 0.0f;

    #define GH_PREFETCH(kt, st)                                                \
    {                                                                          \
        __half* As_ = hsm + (st) * GSTAGE;                                     \
        __half* Bs_ = As_ + GBM * GSTR;                                        \
        const __half* Ag = A  + (size_t)bm * C_ + (kt) * GBK;                  \
        const __half* Bg = Bt + (size_t)bn * C_ + (kt) * GBK;                  \
        _Pragma("unroll")                                                      \
        for (int it = 0; it < 4; it++) {                                       \
            const int idx = it * 256 + tid;                                    \
            const int row = idx >> 3, g = (idx & 7) * 8;                       \
            cpasync16(As_ + row * GSTR + g, Ag + (size_t)row * C_ + g);        \
        }                                                                      \
        _Pragma("unroll")                                                      \
        for (int it = 0; it < 4; it++) {                                       \
            const int idx = it * 256 + tid;                                    \
            const int row = idx >> 3, g = (idx & 7) * 8;                       \
            cpasync16(Bs_ + row * GSTR + g, Bg + (size_t)row * C_ + g);        \
        }                                                                      \
    }

    GH_PREFETCH(0, 0);
    CP_COMMIT();

    for (int kt = 0; kt < GNKT; kt++) {
        if (kt + 1 < GNKT) {
            GH_PREFETCH(kt + 1, (kt + 1) & 1);
            CP_COMMIT();
            cp_wait<1>();
        } else {
            cp_wait<0>();
        }
        __syncthreads();

        const __half* As = hsm + (kt & 1) * GSTAGE;
        const __half* Bs = As + GBM * GSTR;
        const uint32_t as_u = (uint32_t)__cvta_generic_to_shared(As) + lm_off;
        const uint32_t bs_u = (uint32_t)__cvta_generic_to_shared(Bs) + lm_off;

        #pragma unroll
        for (int kk = 0; kk < 4; kk++) {            // K=16 steps
            const int kb = kk * 16;
            uint32_t af[2][4];
            #pragma unroll
            for (int mt = 0; mt < 2; mt++)
                ldsm_x4(af[mt][0], af[mt][1], af[mt][2], af[mt][3],
                        as_u + ((wm * 32 + mt * 16) * GSTR + kb) * 2);
            #pragma unroll
            for (int ntp = 0; ntp < 4; ntp++) {
                uint32_t b0e, b0o, b1e, b1o;
                ldsm_x4(b0e, b0o, b1e, b1o,
                        bs_u + ((wn * 64 + ntp * 16) * GSTR + kb) * 2);
                mma_f16(acc[0][2*ntp],     af[0], b0e, b1e);
                mma_f16(acc[0][2*ntp + 1], af[0], b0o, b1o);
                mma_f16(acc[1][2*ntp],     af[1], b0e, b1e);
                mma_f16(acc[1][2*ntp + 1], af[1], b0o, b1o);
            }
        }
        __syncthreads();
    }

    // ---- Epilogue ----
    if (MODE == 0) {
        float* o = (float*)Co;
        #pragma unroll
        for (int mt = 0; mt < 2; mt++) {
            const int row = bm + wm * 32 + mt * 16 + r;
            #pragma unroll
            for (int nt = 0; nt < 8; nt++) {
                const int col = bn + wn * 64 + nt * 8 + cq * 2;
                *(float2*)(o + (size_t)row * OSTR + col) =
                    make_float2(acc[mt][nt][0], acc[mt][nt][1]);
                *(float2*)(o + (size_t)(row + 8) * OSTR + col) =
                    make_float2(acc[mt][nt][2], acc[mt][nt][3]);
            }
        }
    } else {
        // Fused RoPE + RMSNorm for q/k cols (<2048); v passes through.
        __half* o = (__half*)Co;
        const bool is_v = (bn + wn * 64) >= 2048;
        #pragma unroll
        for (int mt = 0; mt < 2; mt++) {
            #pragma unroll
            for (int rh = 0; rh < 2; rh++) {      // c0,c1 = row r; c2,c3 = r+8
                const int row = bm + wm * 32 + mt * 16 + r + rh * 8;
                const int i0 = rh * 2, i1 = rh * 2 + 1;
                float ov[8][2];
                if (!is_v) {
                    const int t = row & (T_ - 1);
                    float ssum = 0.0f;
                    #pragma unroll
                    for (int nt = 0; nt < 4; nt++) {
                        const int d0 = nt * 8 + cq * 2;
                        const float2 cc = *(const float2*)&cosb[(size_t)t * D_ + d0];
                        const float2 sn = *(const float2*)&sinb[(size_t)t * D_ + d0];
                        const float x1a = acc[mt][nt][i0],     x1b = acc[mt][nt][i1];
                        const float x2a = acc[mt][nt + 4][i0], x2b = acc[mt][nt + 4][i1];
                        ov[nt][0]     = x1a * cc.x - x2a * sn.x;
                        ov[nt][1]     = x1b * cc.y - x2b * sn.y;
                        ov[nt + 4][0] = x1a * sn.x + x2a * cc.x;
                        ov[nt + 4][1] = x1b * sn.y + x2b * cc.y;
                        ssum += ov[nt][0]*ov[nt][0] + ov[nt][1]*ov[nt][1]
                              + ov[nt+4][0]*ov[nt+4][0] + ov[nt+4][1]*ov[nt+4][1];
                    }
                    ssum += __shfl_xor_sync(0xffffffffu, ssum, 1);
                    ssum += __shfl_xor_sync(0xffffffffu, ssum, 2);
                    const float rinv = rsqrtf(ssum * (1.0f / 64.0f) + 1e-6f);
                    #pragma unroll
                    for (int nt = 0; nt < 8; nt++) {
                        ov[nt][0] *= rinv; ov[nt][1] *= rinv;
                    }
                } else {
                    #pragma unroll
                    for (int nt = 0; nt < 8; nt++) {
                        ov[nt][0] = acc[mt][nt][i0];
                        ov[nt][1] = acc[mt][nt][i1];
                    }
                }
                #pragma unroll
                for (int nt = 0; nt < 8; nt++) {
                    const int col = bn + wn * 64 + nt * 8 + cq * 2;
                    __half2 hv = __floats2half2_rn(ov[nt][0], ov[nt][1]);
                    *(uint32_t*)(o + (size_t)row * OSTR + col) = *(uint32_t*)&hv;
                }
            }
        }
    }
}

// ----------------------------------------------------------------------------
// Flash attention v3: fixed-base softmax, register-resident P, 4-stage KV
// ring (prefetch 3 tiles ahead), split-half software pipelining:
//   S_A(cols 0..31) -> exp/pack A -> S_B(cols 32..63) -> PV_A -> exp B -> PV_B
// so independent mma blocks overlap the scalar softmax chains.
// One __syncthreads per tile. 128-row q-tile, 64-row k-tile, 8 warps.
// ----------------------------------------------------------------------------
#define FSTRH 72
#define KVSTG (64 * FSTRH)                       // halfs per tensor per stage
#define NSTG  4
#define FLASH_SMEM ((128*FSTRH + NSTG*2*KVSTG) * 2) // 92160 B
#define SOFTMAX_SCALE 0.180336880f               // 0.125 * log2(e)

__global__ __launch_bounds__(256) void flash_h(
    const __half* __restrict__ QKV, __half* __restrict__ O)
{
    extern __shared__ __half fsm[];
    __half* Pb = fsm;                            // [128][72] (Q staging only)
    const uint32_t pb_u = (uint32_t)__cvta_generic_to_shared(Pb);

    const int tid  = threadIdx.x;
    const int lane = tid & 31;
    const int warp = tid >> 5;         // 0..7
    const int r  = lane >> 2;          // 0..7
    const int cq = lane & 3;           // 0..3
    const int b = blockIdx.z, h = blockIdx.y;
    const int qi = (int)(gridDim.x - 1 - blockIdx.x);   // heavy blocks first
    const int q0 = qi * 128;
    const int m0 = warp * 16;

    const size_t rowstride = N3;           // 3072 halfs

    const int lm_off = ((((lane >> 3) & 1) * 8 + (lane & 7)) * FSTRH
                        + (lane >> 4) * 8) * 2;   // bytes (A/B-type ldmatrix)

    // trans-ldmatrix (V) per-lane decomposition
    const int lm_rr  = lane & 7;
    const int lm_sel = lane >> 3;
    const int lm_kad = ((lm_sel & 1) << 3) + lm_rr;
    const int lm_dad = (lm_sel >> 1) << 3;

    const __half* kbase = QKV + (size_t)(b * T_) * rowstride + C_   + h * D_;
    const __half* vbase = QKV + (size_t)(b * T_) * rowstride + 2*C_ + h * D_;

    #define KV_STAGE_K(s) (fsm + 128 * FSTRH + (s) * 2 * KVSTG)
    #define KV_STAGE_V(s) (KV_STAGE_K(s) + KVSTG)

    #define KVH_PREFETCH(jt, s)                                                \
    {                                                                          \
        __half* Kbuf = KV_STAGE_K(s);                                          \
        __half* Vbuf = KV_STAGE_V(s);                                          \
        _Pragma("unroll")                                                      \
        for (int it = 0; it < 2; it++) {                                       \
            const int idx = it * 256 + tid;                                    \
            const int row = idx >> 3;                                          \
            const int g   = (idx & 7) * 8;                                     \
            const __half* kg = kbase + (size_t)((jt) * 64 + row) * rowstride;  \
            const __half* vg = vbase + (size_t)((jt) * 64 + row) * rowstride;  \
            cpasync16(Kbuf + row * FSTRH + g, kg + g);                         \
            cpasync16(Vbuf + row * FSTRH + g, vg + g);                         \
        }                                                                      \
    }

    const int ntile = 2 * qi + 2;

    // ---- Stage Q into Pb (plain stores); prefetch K/V tiles 0,1,2 ----
    const __half* qb = QKV + (size_t)(b * T_ + q0) * rowstride + h * D_;
    #pragma unroll
    for (int it = 0; it < 4; it++) {
        const int idx = it * 256 + tid;
        const int row = idx >> 3;
        const int g   = (idx & 7) * 8;
        *(uint4*)&Pb[row * FSTRH + g] =
            *(const uint4*)(qb + (size_t)row * rowstride + g);
    }
    KVH_PREFETCH(0, 0); CP_COMMIT();
    if (ntile > 1) { KVH_PREFETCH(1, 1); }
    CP_COMMIT();
    if (ntile > 2) { KVH_PREFETCH(2, 2); }
    CP_COMMIT();
    __syncthreads();          // Q visible

    uint32_t qa[4][4];
    #pragma unroll
    for (int kk = 0; kk < 4; kk++)
        ldsm_x4(qa[kk][0], qa[kk][1], qa[kk][2], qa[kk][3],
                pb_u + (m0 * FSTRH + kk * 16) * 2 + lm_off);

    float l_lo = 0.0f, l_hi = 0.0f;
    float oacc[8][4];
    #pragma unroll
    for (int dt = 0; dt < 8; dt++)
        #pragma unroll
        for (int i = 0; i < 4; i++) oacc[dt][i] = 0.0f;

    for (int jt = 0; jt < ntile; jt++) {
        cp_wait<2>();          // tile jt landed (outstanding: jt+1, jt+2)
        __syncthreads();       // copies visible; readers of stage (jt+3)%4 done
        if (jt + 3 < ntile) { KVH_PREFETCH(jt + 3, (jt + 3) % NSTG); }
        CP_COMMIT();           // keep group numbering uniform

        const __half* Ks = KV_STAGE_K(jt % NSTG);
        const __half* Vs = KV_STAGE_V(jt % NSTG);
        const uint32_t ks_u = (uint32_t)__cvta_generic_to_shared(Ks) + lm_off;
        const uint32_t vs_u = (uint32_t)__cvta_generic_to_shared(Vs);
        const int k0 = jt * 64;
        const bool diag = (jt >= 2 * qi);
        const int row_lo = q0 + m0 + r;
        const int row_hi = row_lo + 8;

        // ======== half A: cols 0..31 (nt 0..3) ========
        float sa[4][4];
        #pragma unroll
        for (int nt = 0; nt < 4; nt++)
            #pragma unroll
            for (int i = 0; i < 4; i++) sa[nt][i] = 0.0f;

        #pragma unroll
        for (int kk = 0; kk < 4; kk++) {
            const int kb2 = kk * 16;
            #pragma unroll
            for (int ntp = 0; ntp < 2; ntp++) {
                uint32_t b0e, b0o, b1e, b1o;
                ldsm_x4(b0e, b0o, b1e, b1o,
                        ks_u + (ntp * 16 * FSTRH + kb2) * 2);
                mma_f16(sa[2*ntp],     qa[kk], b0e, b1e);
                mma_f16(sa[2*ntp + 1], qa[kk], b0o, b1o);
            }
        }

        // exp/pack A
        uint32_t paA[2][4];
        if (diag) {
            #pragma unroll
            for (int nt = 0; nt < 4; nt++) {
                const int c0 = k0 + nt * 8 + cq * 2;
                if (row_lo < c0    ) sa[nt][0] = -1e30f;
                if (row_lo < c0 + 1) sa[nt][1] = -1e30f;
                if (row_hi < c0    ) sa[nt][2] = -1e30f;
                if (row_hi < c0 + 1) sa[nt][3] = -1e30f;
            }
        }
        #pragma unroll
        for (int nt = 0; nt < 4; nt++) {
            sa[nt][0] = ex2f(sa[nt][0] * SOFTMAX_SCALE);
            sa[nt][1] = ex2f(sa[nt][1] * SOFTMAX_SCALE);
            sa[nt][2] = ex2f(sa[nt][2] * SOFTMAX_SCALE);
            sa[nt][3] = ex2f(sa[nt][3] * SOFTMAX_SCALE);
            l_lo += sa[nt][0] + sa[nt][1];
            l_hi += sa[nt][2] + sa[nt][3];
        }
        #pragma unroll
        for (int kk = 0; kk < 2; kk++) {
            paA[kk][0] = packh2(sa[2*kk][0],     sa[2*kk][1]);
            paA[kk][1] = packh2(sa[2*kk][2],     sa[2*kk][3]);
            paA[kk][2] = packh2(sa[2*kk + 1][0], sa[2*kk + 1][1]);
            paA[kk][3] = packh2(sa[2*kk + 1][2], sa[2*kk + 1][3]);
        }

        // ======== half B: cols 32..63 (nt 4..7) -> reuse sa ========
        float sb[4][4];
        #pragma unroll
        for (int nt = 0; nt < 4; nt++)
            #pragma unroll
            for (int i = 0; i < 4; i++) sb[nt][i] = 0.0f;

        #pragma unroll
        for (int kk = 0; kk < 4; kk++) {
            const int kb2 = kk * 16;
            #pragma unroll
            for (int ntp = 2; ntp < 4; ntp++) {
                uint32_t b0e, b0o, b1e, b1o;
                ldsm_x4(b0e, b0o, b1e, b1o,
                        ks_u + (ntp * 16 * FSTRH + kb2) * 2);
                mma_f16(sb[2*(ntp-2)],     qa[kk], b0e, b1e);
                mma_f16(sb[2*(ntp-2) + 1], qa[kk], b0o, b1o);
            }
        }

        // ---- PV half A: V k-rows 0..31 (kk 0..1) ----
        #pragma unroll
        for (int kk = 0; kk < 2; kk++) {
            const int kb2 = kk * 16;
            #pragma unroll
            for (int dtp = 0; dtp < 4; dtp++) {
                uint32_t v0, v1, v2, v3;
                const uint32_t addr = vs_u +
                    (uint32_t)(((kb2 + lm_kad) * FSTRH + dtp * 16 + lm_dad) * 2);
                ldsm_x4_t(v0, v1, v2, v3, addr);
                mma_f16(oacc[2*dtp],     paA[kk], v0, v1);
                mma_f16(oacc[2*dtp + 1], paA[kk], v2, v3);
            }
        }

        // exp/pack B
        uint32_t paB[2][4];
        if (diag) {
            #pragma unroll
            for (int nt = 0; nt < 4; nt++) {
                const int c0 = k0 + 32 + nt * 8 + cq * 2;
                if (row_lo < c0    ) sb[nt][0] = -1e30f;
                if (row_lo < c0 + 1) sb[nt][1] = -1e30f;
                if (row_hi < c0    ) sb[nt][2] = -1e30f;
                if (row_hi < c0 + 1) sb[nt][3] = -1e30f;
            }
        }
        #pragma unroll
        for (int nt = 0; nt < 4; nt++) {
            sb[nt][0] = ex2f(sb[nt][0] * SOFTMAX_SCALE);
            sb[nt][1] = ex2f(sb[nt][1] * SOFTMAX_SCALE);
            sb[nt][2] = ex2f(sb[nt][2] * SOFTMAX_SCALE);
            sb[nt][3] = ex2f(sb[nt][3] * SOFTMAX_SCALE);
            l_lo += sb[nt][0] + sb[nt][1];
            l_hi += sb[nt][2] + sb[nt][3];
        }
        #pragma unroll
        for (int kk = 0; kk < 2; kk++) {
            paB[kk][0] = packh2(sb[2*kk][0],     sb[2*kk][1]);
            paB[kk][1] = packh2(sb[2*kk][2],     sb[2*kk][3]);
            paB[kk][2] = packh2(sb[2*kk + 1][0], sb[2*kk + 1][1]);
            paB[kk][3] = packh2(sb[2*kk + 1][2], sb[2*kk + 1][3]);
        }

        // ---- PV half B: V k-rows 32..63 (kk 2..3) ----
        #pragma unroll
        for (int kk = 0; kk < 2; kk++) {
            const int kb2 = (kk + 2) * 16;
            #pragma unroll
            for (int dtp = 0; dtp < 4; dtp++) {
                uint32_t v0, v1, v2, v3;
                const uint32_t addr = vs_u +
                    (uint32_t)(((kb2 + lm_kad) * FSTRH + dtp * 16 + lm_dad) * 2);
                ldsm_x4_t(v0, v1, v2, v3, addr);
                mma_f16(oacc[2*dtp],     paB[kk], v0, v1);
                mma_f16(oacc[2*dtp + 1], paB[kk], v2, v3);
            }
        }
    }

    // ---- final l reduction across cq group, normalize + store ----
    l_lo += __shfl_xor_sync(0xffffffffu, l_lo, 1);
    l_lo += __shfl_xor_sync(0xffffffffu, l_lo, 2);
    l_hi += __shfl_xor_sync(0xffffffffu, l_hi, 1);
    l_hi += __shfl_xor_sync(0xffffffffu, l_hi, 2);
    const float inv_lo = 1.0f / l_lo;
    const float inv_hi = 1.0f / l_hi;

    __half* ob = O + ((size_t)(b * T_ + q0) * H_ + h) * D_;
    #pragma unroll
    for (int dt = 0; dt < 8; dt++) {
        const int cc = dt * 8 + cq * 2;
        const uint32_t h0 = packh2(oacc[dt][0] * inv_lo, oacc[dt][1] * inv_lo);
        const uint32_t h1 = packh2(oacc[dt][2] * inv_hi, oacc[dt][3] * inv_hi);
        *(uint32_t*)(ob + (size_t)(m0 + r) * C_ + cc)     = h0;
        *(uint32_t*)(ob + (size_t)(m0 + r + 8) * C_ + cc) = h1;
    }
}

// ----------------------------------------------------------------------------
// Launch
// ----------------------------------------------------------------------------
extern "C" void kernel_launch(void* const* d_in, const int* in_sizes, int n_in,
                              void* d_out, int out_size)
{
    const float* x    = (const float*)d_in[0];
    const float* cosb = (const float*)d_in[1];
    const float* sinb = (const float*)d_in[2];
    const float* Wq   = (const float*)d_in[3];
    const float* Wk   = (const float*)d_in[4];
    const float* Wv   = (const float*)d_in[5];
    const float* Wp   = (const float*)d_in[6];
    float* out = (float*)d_out;

    __half *xh, *qkv, *yh, *wcat, *wpt;
    cudaGetSymbolAddress((void**)&xh,   g_xh);
    cudaGetSymbolAddress((void**)&qkv,  g_qkv);
    cudaGetSymbolAddress((void**)&yh,   g_yh);
    cudaGetSymbolAddress((void**)&wcat, g_wcat);
    cudaGetSymbolAddress((void**)&wpt,  g_wpt);

    cudaFuncSetAttribute(gemm2<1>,
        cudaFuncAttributeMaxDynamicSharedMemorySize, GEMM_SMEM);
    cudaFuncSetAttribute(gemm2<0>,
        cudaFuncAttributeMaxDynamicSharedMemorySize, GEMM_SMEM);
    cudaFuncSetAttribute(flash_h,
        cudaFuncAttributeMaxDynamicSharedMemorySize, FLASH_SMEM);

    // Pre-pass
    conv_xh<<<(M_ * C_) / (256 * 4), 256>>>(x, xh);
    dim3 tgrid(C_ / 32, C_ / 32, 4);
    trans_all<<<tgrid, 256>>>(Wq, Wk, Wv, Wp, wcat, wpt);

    // Fused QKV projection + RoPE + RMSNorm
    dim3 qgrid(N3 / GBN, M_ / GBM);   // (24, 32)
    gemm2<1><<<qgrid, 256, GEMM_SMEM>>>(xh, wcat, qkv, cosb, sinb);

    // Attention
    dim3 fgrid(T_ / 128, H_, B_);     // (16, 16, 2)
    flash_h<<<fgrid, 256, FLASH_SMEM>>>(qkv, yh);

    // Output projection (fp32 out)
    dim3 pgrid(C_ / GBN, M_ / GBM);   // (8, 32)
    gemm2<0><<<pgrid, 256, GEMM_SMEM>>>(yh, wpt, out, cosb, sinb);
}

// round 12
// speedup vs baseline: 1.0004x; 1.0004x over previous
#include <cuda_runtime.h>
#include <cuda_fp16.h>
#include <math.h>
#include <stdint.h>

// Problem constants (B=2, T=2048, C=1024, H=16, D=64)
#define B_  2
#define T_  2048
#define C_  1024
#define H_  16
#define D_  64
#define M_  (B_*T_)        // 4096 rows
#define N3  (3*C_)         // 3072

// Scratch
__device__ __half g_xh  [M_*C_];
__device__ __half g_qkv [M_*N3];     // [row][3072]: q | k | v
__device__ __half g_yh  [M_*C_];
__device__ __half g_wcat[N3*C_];     // transposed [n][k], q|k|v stacked
__device__ __half g_wpt [C_*C_];

// ----------------------------------------------------------------------------
// Helpers
// ----------------------------------------------------------------------------
__device__ __forceinline__ void mma_f16(float* c, const uint32_t* a,
                                        uint32_t b0, uint32_t b1) {
    asm volatile(
        "mma.sync.aligned.m16n8k16.row.col.f32.f16.f16.f32 "
        "{%0,%1,%2,%3}, {%4,%5,%6,%7}, {%8,%9}, {%0,%1,%2,%3};"
        : "+f"(c[0]), "+f"(c[1]), "+f"(c[2]), "+f"(c[3])
        : "r"(a[0]), "r"(a[1]), "r"(a[2]), "r"(a[3]), "r"(b0), "r"(b1));
}

__device__ __forceinline__ void cpasync16(void* s, const void* g) {
    uint32_t sp = (uint32_t)__cvta_generic_to_shared(s);
    asm volatile("cp.async.cg.shared.global [%0], [%1], 16;" :: "r"(sp), "l"(g));
}
#define CP_COMMIT() asm volatile("cp.async.commit_group;" ::: "memory")
template <int N> __device__ __forceinline__ void cp_wait() {
    asm volatile("cp.async.wait_group %0;" :: "n"(N) : "memory");
}

__device__ __forceinline__ void ldsm_x4(uint32_t& r0, uint32_t& r1,
                                        uint32_t& r2, uint32_t& r3,
                                        uint32_t saddr) {
    asm volatile(
        "ldmatrix.sync.aligned.m8n8.x4.shared.b16 {%0,%1,%2,%3}, [%4];"
        : "=r"(r0), "=r"(r1), "=r"(r2), "=r"(r3) : "r"(saddr));
}
__device__ __forceinline__ void ldsm_x4_t(uint32_t& r0, uint32_t& r1,
                                          uint32_t& r2, uint32_t& r3,
                                          uint32_t saddr) {
    asm volatile(
        "ldmatrix.sync.aligned.m8n8.x4.trans.shared.b16 {%0,%1,%2,%3}, [%4];"
        : "=r"(r0), "=r"(r1), "=r"(r2), "=r"(r3) : "r"(saddr));
}

__device__ __forceinline__ float ex2f(float x) {
    float y;
    asm("ex2.approx.ftz.f32 %0, %1;" : "=f"(y) : "f"(x));
    return y;
}

__device__ __forceinline__ uint32_t packh2(float a, float b) {
    __half2 h = __floats2half2_rn(a, b);
    return *(uint32_t*)&h;
}

// ----------------------------------------------------------------------------
// Pre-pass: x -> half ; all 4 weights -> half transposed [n][k] (one kernel)
// ----------------------------------------------------------------------------
__global__ __launch_bounds__(256) void conv_xh(
    const float* __restrict__ in, __half* __restrict__ outp)
{
    const int i = blockIdx.x * 256 + threadIdx.x;
    float4 v = ((const float4*)in)[i];
    __half2 h0 = __floats2half2_rn(v.x, v.y);
    __half2 h1 = __floats2half2_rn(v.z, v.w);
    ((uint2*)outp)[i] = make_uint2(*(uint32_t*)&h0, *(uint32_t*)&h1);
}

__global__ __launch_bounds__(256) void trans_all(
    const float* __restrict__ Wq, const float* __restrict__ Wk,
    const float* __restrict__ Wv, const float* __restrict__ Wp,
    __half* __restrict__ wcat, __half* __restrict__ wpt)
{
    __shared__ float t[32][33];
    const int z = blockIdx.z;
    const float* W = (z == 0) ? Wq : (z == 1) ? Wk : (z == 2) ? Wv : Wp;
    __half* Wt = (z < 3) ? (wcat + (size_t)z * C_ * C_) : wpt;

    const int tx = threadIdx.x & 31;
    const int ty = threadIdx.x >> 5;
    const int bx = blockIdx.x * 32;       // n block
    const int by = blockIdx.y * 32;       // k block
    #pragma unroll
    for (int i = ty; i < 32; i += 8)
        t[i][tx] = W[(size_t)(by + i) * C_ + bx + tx];
    __syncthreads();
    #pragma unroll
    for (int i = ty; i < 32; i += 8)
        Wt[(size_t)(bx + i) * C_ + by + tx] = __float2half(t[tx][i]);
}

// ----------------------------------------------------------------------------
// FP16 GEMM with software-pipelined ldmatrix fragment loads.
// D[m][n] = sum_k A[m][k]*Bt[n][k].
// MODE 1: N=3072, half out stride 3072, fused RoPE+RMSNorm on cols<2048.
// MODE 0: N=1024, fp32 out stride 1024.
// ----------------------------------------------------------------------------
#define GBM 128
#define GBN 128
#define GBK 64
#define GSTR 72
#define GNKT (C_/GBK)                         // 16
#define GSTAGE ((GBM + GBN) * GSTR)           // halfs per stage
#define GEMM_SMEM (2 * GSTAGE * 2)            // 73728 B

template<int MODE>
__global__ __launch_bounds__(256, 2) void gemm2(
    const __half* __restrict__ A, const __half* __restrict__ Bt, void* Co,
    const float* __restrict__ cosb, const float* __restrict__ sinb)
{
    extern __shared__ __half hsm[];
    constexpr int OSTR = MODE ? N3 : C_;

    const int tid  = threadIdx.x;
    const int lane = tid & 31;
    const int wid  = tid >> 5;
    const int wm   = wid >> 1;       // 0..3
    const int wn   = wid & 1;        // 0..1
    const int bm = blockIdx.y * GBM;
    const int bn = blockIdx.x * GBN;
    const int r  = lane >> 2;        // 0..7
    const int cq = lane & 3;         // 0..3

    const int lm_off = ((((lane >> 3) & 1) * 8 + (lane & 7)) * GSTR
                        + (lane >> 4) * 8) * 2;   // bytes

    float acc[2][8][4];
    #pragma unroll
    for (int mt = 0; mt < 2; mt++)
        #pragma unroll
        for (int nt = 0; nt < 8; nt++)
            #pragma unroll
            for (int i = 0; i < 4; i++) acc[mt][nt][i] = 0.0f;

    #define GH_PREFETCH(kt, st)                                                \
    {                                                                          \
        __half* As_ = hsm + (st) * GSTAGE;                                     \
        __half* Bs_ = As_ + GBM * GSTR;                                        \
        const __half* Ag = A  + (size_t)bm * C_ + (kt) * GBK;                  \
        const __half* Bg = Bt + (size_t)bn * C_ + (kt) * GBK;                  \
        _Pragma("unroll")                                                      \
        for (int it = 0; it < 4; it++) {                                       \
            const int idx = it * 256 + tid;                                    \
            const int row = idx >> 3, g = (idx & 7) * 8;                       \
            cpasync16(As_ + row * GSTR + g, Ag + (size_t)row * C_ + g);        \
        }                                                                      \
        _Pragma("unroll")                                                      \
        for (int it = 0; it < 4; it++) {                                       \
            const int idx = it * 256 + tid;                                    \
            const int row = idx >> 3, g = (idx & 7) * 8;                       \
            cpasync16(Bs_ + row * GSTR + g, Bg + (size_t)row * C_ + g);        \
        }                                                                      \
    }

    GH_PREFETCH(0, 0);
    CP_COMMIT();

    for (int kt = 0; kt < GNKT; kt++) {
        if (kt + 1 < GNKT) {
            GH_PREFETCH(kt + 1, (kt + 1) & 1);
            CP_COMMIT();
            cp_wait<1>();
        } else {
            cp_wait<0>();
        }
        __syncthreads();

        const __half* As = hsm + (kt & 1) * GSTAGE;
        const __half* Bs = As + GBM * GSTR;
        const uint32_t as_u = (uint32_t)__cvta_generic_to_shared(As) + lm_off;
        const uint32_t bs_u = (uint32_t)__cvta_generic_to_shared(Bs) + lm_off;

        // Software-pipelined fragment loads: step s = kk*4 + ntp.
        // B double-buffered per step; A double-buffered per kk.
        uint32_t afb[2][2][4];   // [kk parity][mt][reg]
        uint32_t bfb[2][4];      // [s parity][reg] = {b0e, b0o, b1e, b1o}

        #define LOAD_A(kkx, buf)                                               \
            _Pragma("unroll")                                                  \
            for (int mt = 0; mt < 2; mt++)                                     \
                ldsm_x4(afb[buf][mt][0], afb[buf][mt][1],                      \
                        afb[buf][mt][2], afb[buf][mt][3],                      \
                        as_u + ((wm * 32 + mt * 16) * GSTR + (kkx) * 16) * 2);
        #define LOAD_B(kkx, ntpx, buf)                                         \
            ldsm_x4(bfb[buf][0], bfb[buf][1], bfb[buf][2], bfb[buf][3],        \
                    bs_u + ((wn * 64 + (ntpx) * 16) * GSTR + (kkx) * 16) * 2);

        LOAD_A(0, 0);
        LOAD_B(0, 0, 0);

        #pragma unroll
        for (int s = 0; s < 16; s++) {
            const int kk  = s >> 2, ntp = s & 3;
            const int cur = s & 1,  nxt = cur ^ 1;
            if (s < 15) {
                const int s1 = s + 1;
                const int kk1 = s1 >> 2, ntp1 = s1 & 3;
                LOAD_B(kk1, ntp1, nxt);
                if (ntp == 3) { LOAD_A(kk1, kk1 & 1); }
            }
            const int ap = kk & 1;
            mma_f16(acc[0][2*ntp],     afb[ap][0], bfb[cur][0], bfb[cur][2]);
            mma_f16(acc[0][2*ntp + 1], afb[ap][0], bfb[cur][1], bfb[cur][3]);
            mma_f16(acc[1][2*ntp],     afb[ap][1], bfb[cur][0], bfb[cur][2]);
            mma_f16(acc[1][2*ntp + 1], afb[ap][1], bfb[cur][1], bfb[cur][3]);
        }
        #undef LOAD_A
        #undef LOAD_B
        __syncthreads();
    }

    // ---- Epilogue ----
    if (MODE == 0) {
        float* o = (float*)Co;
        #pragma unroll
        for (int mt = 0; mt < 2; mt++) {
            const int row = bm + wm * 32 + mt * 16 + r;
            #pragma unroll
            for (int nt = 0; nt < 8; nt++) {
                const int col = bn + wn * 64 + nt * 8 + cq * 2;
                *(float2*)(o + (size_t)row * OSTR + col) =
                    make_float2(acc[mt][nt][0], acc[mt][nt][1]);
                *(float2*)(o + (size_t)(row + 8) * OSTR + col) =
                    make_float2(acc[mt][nt][2], acc[mt][nt][3]);
            }
        }
    } else {
        // Fused RoPE + RMSNorm for q/k cols (<2048); v passes through.
        __half* o = (__half*)Co;
        const bool is_v = (bn + wn * 64) >= 2048;
        #pragma unroll
        for (int mt = 0; mt < 2; mt++) {
            #pragma unroll
            for (int rh = 0; rh < 2; rh++) {      // c0,c1 = row r; c2,c3 = r+8
                const int row = bm + wm * 32 + mt * 16 + r + rh * 8;
                const int i0 = rh * 2, i1 = rh * 2 + 1;
                float ov[8][2];
                if (!is_v) {
                    const int t = row & (T_ - 1);
                    float ssum = 0.0f;
                    #pragma unroll
                    for (int nt = 0; nt < 4; nt++) {
                        const int d0 = nt * 8 + cq * 2;
                        const float2 cc = *(const float2*)&cosb[(size_t)t * D_ + d0];
                        const float2 sn = *(const float2*)&sinb[(size_t)t * D_ + d0];
                        const float x1a = acc[mt][nt][i0],     x1b = acc[mt][nt][i1];
                        const float x2a = acc[mt][nt + 4][i0], x2b = acc[mt][nt + 4][i1];
                        ov[nt][0]     = x1a * cc.x - x2a * sn.x;
                        ov[nt][1]     = x1b * cc.y - x2b * sn.y;
                        ov[nt + 4][0] = x1a * sn.x + x2a * cc.x;
                        ov[nt + 4][1] = x1b * sn.y + x2b * cc.y;
                        ssum += ov[nt][0]*ov[nt][0] + ov[nt][1]*ov[nt][1]
                              + ov[nt+4][0]*ov[nt+4][0] + ov[nt+4][1]*ov[nt+4][1];
                    }
                    ssum += __shfl_xor_sync(0xffffffffu, ssum, 1);
                    ssum += __shfl_xor_sync(0xffffffffu, ssum, 2);
                    const float rinv = rsqrtf(ssum * (1.0f / 64.0f) + 1e-6f);
                    #pragma unroll
                    for (int nt = 0; nt < 8; nt++) {
                        ov[nt][0] *= rinv; ov[nt][1] *= rinv;
                    }
                } else {
                    #pragma unroll
                    for (int nt = 0; nt < 8; nt++) {
                        ov[nt][0] = acc[mt][nt][i0];
                        ov[nt][1] = acc[mt][nt][i1];
                    }
                }
                #pragma unroll
                for (int nt = 0; nt < 8; nt++) {
                    const int col = bn + wn * 64 + nt * 8 + cq * 2;
                    __half2 hv = __floats2half2_rn(ov[nt][0], ov[nt][1]);
                    *(uint32_t*)(o + (size_t)row * OSTR + col) = *(uint32_t*)&hv;
                }
            }
        }
    }
}

// ----------------------------------------------------------------------------
// Flash attention (round-10 version, verbatim): fixed-base softmax,
// register-resident P, 3-stage KV ring, one barrier per tile.
// ----------------------------------------------------------------------------
#define FSTRH 72
#define KVSTG (64 * FSTRH)                       // halfs per tensor per stage
#define FLASH_SMEM ((128*FSTRH + 3*2*KVSTG) * 2) // 73728 B
#define SOFTMAX_SCALE 0.180336880f               // 0.125 * log2(e)

__global__ __launch_bounds__(256) void flash_h(
    const __half* __restrict__ QKV, __half* __restrict__ O)
{
    extern __shared__ __half fsm[];
    __half* Pb = fsm;                            // [128][72] (Q staging only)
    const uint32_t pb_u = (uint32_t)__cvta_generic_to_shared(Pb);

    const int tid  = threadIdx.x;
    const int lane = tid & 31;
    const int warp = tid >> 5;         // 0..7
    const int r  = lane >> 2;          // 0..7
    const int cq = lane & 3;           // 0..3
    const int b = blockIdx.z, h = blockIdx.y;
    const int qi = (int)(gridDim.x - 1 - blockIdx.x);   // heavy blocks first
    const int q0 = qi * 128;
    const int m0 = warp * 16;

    const size_t rowstride = N3;           // 3072 halfs

    const int lm_off = ((((lane >> 3) & 1) * 8 + (lane & 7)) * FSTRH
                        + (lane >> 4) * 8) * 2;   // bytes (A/B-type ldmatrix)

    // trans-ldmatrix (V) per-lane decomposition
    const int lm_rr  = lane & 7;
    const int lm_sel = lane >> 3;
    const int lm_kad = ((lm_sel & 1) << 3) + lm_rr;
    const int lm_dad = (lm_sel >> 1) << 3;

    const __half* kbase = QKV + (size_t)(b * T_) * rowstride + C_   + h * D_;
    const __half* vbase = QKV + (size_t)(b * T_) * rowstride + 2*C_ + h * D_;

    #define KV_STAGE_K(s) (fsm + 128 * FSTRH + (s) * 2 * KVSTG)
    #define KV_STAGE_V(s) (KV_STAGE_K(s) + KVSTG)

    #define KVH_PREFETCH(jt, s)                                                \
    {                                                                          \
        __half* Kbuf = KV_STAGE_K(s);                                          \
        __half* Vbuf = KV_STAGE_V(s);                                          \
        _Pragma("unroll")                                                      \
        for (int it = 0; it < 2; it++) {                                       \
            const int idx = it * 256 + tid;                                    \
            const int row = idx >> 3;                                          \
            const int g   = (idx & 7) * 8;                                     \
            const __half* kg = kbase + (size_t)((jt) * 64 + row) * rowstride;  \
            const __half* vg = vbase + (size_t)((jt) * 64 + row) * rowstride;  \
            cpasync16(Kbuf + row * FSTRH + g, kg + g);                         \
            cpasync16(Vbuf + row * FSTRH + g, vg + g);                         \
        }                                                                      \
    }

    const int ntile = 2 * qi + 2;

    // ---- Stage Q into Pb (plain stores); prefetch K/V tiles 0,1 ----
    const __half* qb = QKV + (size_t)(b * T_ + q0) * rowstride + h * D_;
    #pragma unroll
    for (int it = 0; it < 4; it++) {
        const int idx = it * 256 + tid;
        const int row = idx >> 3;
        const int g   = (idx & 7) * 8;
        *(uint4*)&Pb[row * FSTRH + g] =
            *(const uint4*)(qb + (size_t)row * rowstride + g);
    }
    KVH_PREFETCH(0, 0); CP_COMMIT();
    if (ntile > 1) { KVH_PREFETCH(1, 1); }
    CP_COMMIT();
    __syncthreads();          // Q visible

    uint32_t qa[4][4];
    #pragma unroll
    for (int kk = 0; kk < 4; kk++)
        ldsm_x4(qa[kk][0], qa[kk][1], qa[kk][2], qa[kk][3],
                pb_u + (m0 * FSTRH + kk * 16) * 2 + lm_off);

    float l_lo = 0.0f, l_hi = 0.0f;
    float oacc[8][4];
    #pragma unroll
    for (int dt = 0; dt < 8; dt++)
        #pragma unroll
        for (int i = 0; i < 4; i++) oacc[dt][i] = 0.0f;

    for (int jt = 0; jt < ntile; jt++) {
        cp_wait<1>();          // stage jt data landed (groups: jt done)
        __syncthreads();       // all copies visible; readers of stage (jt+2)%3 done
        if (jt + 2 < ntile) { KVH_PREFETCH(jt + 2, (jt + 2) % 3); }
        CP_COMMIT();           // keep group numbering uniform

        const __half* Ks = KV_STAGE_K(jt % 3);
        const __half* Vs = KV_STAGE_V(jt % 3);
        const uint32_t ks_u = (uint32_t)__cvta_generic_to_shared(Ks) + lm_off;
        const uint32_t vs_u = (uint32_t)__cvta_generic_to_shared(Vs);
        const int k0 = jt * 64;

        // ---- S = Q @ K^T ----
        float sacc[8][4];
        #pragma unroll
        for (int nt = 0; nt < 8; nt++)
            #pragma unroll
            for (int i = 0; i < 4; i++) sacc[nt][i] = 0.0f;

        #pragma unroll
        for (int kk = 0; kk < 4; kk++) {
            const int kb2 = kk * 16;
            #pragma unroll
            for (int ntp = 0; ntp < 4; ntp++) {
                uint32_t b0e, b0o, b1e, b1o;
                ldsm_x4(b0e, b0o, b1e, b1o,
                        ks_u + (ntp * 16 * FSTRH + kb2) * 2);
                mma_f16(sacc[2*ntp],     qa[kk], b0e, b1e);
                mma_f16(sacc[2*ntp + 1], qa[kk], b0o, b1o);
            }
        }

        // ---- mask (diagonal tiles only) + exp2(s * scale) ----
        if (jt >= 2 * qi) {
            const int row_lo = q0 + m0 + r;
            const int row_hi = row_lo + 8;
            #pragma unroll
            for (int nt = 0; nt < 8; nt++) {
                const int c0 = k0 + nt * 8 + cq * 2;
                if (row_lo < c0    ) sacc[nt][0] = -1e30f;
                if (row_lo < c0 + 1) sacc[nt][1] = -1e30f;
                if (row_hi < c0    ) sacc[nt][2] = -1e30f;
                if (row_hi < c0 + 1) sacc[nt][3] = -1e30f;
            }
        }
        #pragma unroll
        for (int nt = 0; nt < 8; nt++) {
            sacc[nt][0] = ex2f(sacc[nt][0] * SOFTMAX_SCALE);
            sacc[nt][1] = ex2f(sacc[nt][1] * SOFTMAX_SCALE);
            sacc[nt][2] = ex2f(sacc[nt][2] * SOFTMAX_SCALE);
            sacc[nt][3] = ex2f(sacc[nt][3] * SOFTMAX_SCALE);
            l_lo += sacc[nt][0] + sacc[nt][1];
            l_hi += sacc[nt][2] + sacc[nt][3];
        }

        // ---- O += P @ V (P straight from registers; C-frag == A-frag) ----
        #pragma unroll
        for (int kk = 0; kk < 4; kk++) {
            uint32_t pa[4];
            pa[0] = packh2(sacc[2*kk][0],     sacc[2*kk][1]);
            pa[1] = packh2(sacc[2*kk][2],     sacc[2*kk][3]);
            pa[2] = packh2(sacc[2*kk + 1][0], sacc[2*kk + 1][1]);
            pa[3] = packh2(sacc[2*kk + 1][2], sacc[2*kk + 1][3]);
            const int kb2 = kk * 16;
            #pragma unroll
            for (int dtp = 0; dtp < 4; dtp++) {
                uint32_t v0, v1, v2, v3;
                const uint32_t addr = vs_u +
                    (uint32_t)(((kb2 + lm_kad) * FSTRH + dtp * 16 + lm_dad) * 2);
                ldsm_x4_t(v0, v1, v2, v3, addr);
                mma_f16(oacc[2*dtp],     pa, v0, v1);
                mma_f16(oacc[2*dtp + 1], pa, v2, v3);
            }
        }
    }

    // ---- final l reduction across cq group, normalize + store ----
    l_lo += __shfl_xor_sync(0xffffffffu, l_lo, 1);
    l_lo += __shfl_xor_sync(0xffffffffu, l_lo, 2);
    l_hi += __shfl_xor_sync(0xffffffffu, l_hi, 1);
    l_hi += __shfl_xor_sync(0xffffffffu, l_hi, 2);
    const float inv_lo = 1.0f / l_lo;
    const float inv_hi = 1.0f / l_hi;

    __half* ob = O + ((size_t)(b * T_ + q0) * H_ + h) * D_;
    #pragma unroll
    for (int dt = 0; dt < 8; dt++) {
        const int cc = dt * 8 + cq * 2;
        const uint32_t h0 = packh2(oacc[dt][0] * inv_lo, oacc[dt][1] * inv_lo);
        const uint32_t h1 = packh2(oacc[dt][2] * inv_hi, oacc[dt][3] * inv_hi);
        *(uint32_t*)(ob + (size_t)(m0 + r) * C_ + cc)     = h0;
        *(uint32_t*)(ob + (size_t)(m0 + r + 8) * C_ + cc) = h1;
    }
}

// ----------------------------------------------------------------------------
// Launch
// ----------------------------------------------------------------------------
extern "C" void kernel_launch(void* const* d_in, const int* in_sizes, int n_in,
                              void* d_out, int out_size)
{
    const float* x    = (const float*)d_in[0];
    const float* cosb = (const float*)d_in[1];
    const float* sinb = (const float*)d_in[2];
    const float* Wq   = (const float*)d_in[3];
    const float* Wk   = (const float*)d_in[4];
    const float* Wv   = (const float*)d_in[5];
    const float* Wp   = (const float*)d_in[6];
    float* out = (float*)d_out;

    __half *xh, *qkv, *yh, *wcat, *wpt;
    cudaGetSymbolAddress((void**)&xh,   g_xh);
    cudaGetSymbolAddress((void**)&qkv,  g_qkv);
    cudaGetSymbolAddress((void**)&yh,   g_yh);
    cudaGetSymbolAddress((void**)&wcat, g_wcat);
    cudaGetSymbolAddress((void**)&wpt,  g_wpt);

    cudaFuncSetAttribute(gemm2<1>,
        cudaFuncAttributeMaxDynamicSharedMemorySize, GEMM_SMEM);
    cudaFuncSetAttribute(gemm2<0>,
        cudaFuncAttributeMaxDynamicSharedMemorySize, GEMM_SMEM);
    cudaFuncSetAttribute(flash_h,
        cudaFuncAttributeMaxDynamicSharedMemorySize, FLASH_SMEM);

    // Pre-pass
    conv_xh<<<(M_ * C_) / (256 * 4), 256>>>(x, xh);
    dim3 tgrid(C_ / 32, C_ / 32, 4);
    trans_all<<<tgrid, 256>>>(Wq, Wk, Wv, Wp, wcat, wpt);

    // Fused QKV projection + RoPE + RMSNorm
    dim3 qgrid(N3 / GBN, M_ / GBM);   // (24, 32)
    gemm2<1><<<qgrid, 256, GEMM_SMEM>>>(xh, wcat, qkv, cosb, sinb);

    // Attention
    dim3 fgrid(T_ / 128, H_, B_);     // (16, 16, 2)
    flash_h<<<fgrid, 256, FLASH_SMEM>>>(qkv, yh);

    // Output projection (fp32 out)
    dim3 pgrid(C_ / GBN, M_ / GBM);   // (8, 32)
    gemm2<0><<<pgrid, 256, GEMM_SMEM>>>(yh, wpt, out, cosb, sinb);
}

// round 14
// speedup vs baseline: 1.0152x; 1.0148x over previous
#include <cuda_runtime.h>
#include <cuda_fp16.h>
#include <math.h>
#include <stdint.h>

// Problem constants (B=2, T=2048, C=1024, H=16, D=64)
#define B_  2
#define T_  2048
#define C_  1024
#define H_  16
#define D_  64
#define M_  (B_*T_)        // 4096 rows
#define N3  (3*C_)         // 3072

// Scratch
__device__ __half g_xh  [M_*C_];
__device__ __half g_qkv [M_*N3];     // [row][3072]: q | k | v
__device__ __half g_yh  [M_*C_];
__device__ __half g_wcat[N3*C_];     // transposed [n][k], q|k|v stacked
__device__ __half g_wpt [C_*C_];

// ----------------------------------------------------------------------------
// Helpers
// ----------------------------------------------------------------------------
__device__ __forceinline__ void mma_f16(float* c, const uint32_t* a,
                                        uint32_t b0, uint32_t b1) {
    asm volatile(
        "mma.sync.aligned.m16n8k16.row.col.f32.f16.f16.f32 "
        "{%0,%1,%2,%3}, {%4,%5,%6,%7}, {%8,%9}, {%0,%1,%2,%3};"
        : "+f"(c[0]), "+f"(c[1]), "+f"(c[2]), "+f"(c[3])
        : "r"(a[0]), "r"(a[1]), "r"(a[2]), "r"(a[3]), "r"(b0), "r"(b1));
}

__device__ __forceinline__ void cpasync16(void* s, const void* g) {
    uint32_t sp = (uint32_t)__cvta_generic_to_shared(s);
    asm volatile("cp.async.cg.shared.global [%0], [%1], 16;" :: "r"(sp), "l"(g));
}
#define CP_COMMIT() asm volatile("cp.async.commit_group;" ::: "memory")
template <int N> __device__ __forceinline__ void cp_wait() {
    asm volatile("cp.async.wait_group %0;" :: "n"(N) : "memory");
}

__device__ __forceinline__ void ldsm_x4(uint32_t& r0, uint32_t& r1,
                                        uint32_t& r2, uint32_t& r3,
                                        uint32_t saddr) {
    asm volatile(
        "ldmatrix.sync.aligned.m8n8.x4.shared.b16 {%0,%1,%2,%3}, [%4];"
        : "=r"(r0), "=r"(r1), "=r"(r2), "=r"(r3) : "r"(saddr));
}
__device__ __forceinline__ void ldsm_x4_t(uint32_t& r0, uint32_t& r1,
                                          uint32_t& r2, uint32_t& r3,
                                          uint32_t saddr) {
    asm volatile(
        "ldmatrix.sync.aligned.m8n8.x4.trans.shared.b16 {%0,%1,%2,%3}, [%4];"
        : "=r"(r0), "=r"(r1), "=r"(r2), "=r"(r3) : "r"(saddr));
}

__device__ __forceinline__ float ex2f(float x) {
    float y;
    asm("ex2.approx.ftz.f32 %0, %1;" : "=f"(y) : "f"(x));
    return y;
}

__device__ __forceinline__ uint32_t packh2(float a, float b) {
    __half2 h = __floats2half2_rn(a, b);
    return *(uint32_t*)&h;
}

// ----------------------------------------------------------------------------
// Fused pre-pass (one launch): z=0..3 -> W transpose+half; z=4 -> x to half.
// ----------------------------------------------------------------------------
__global__ __launch_bounds__(256) void prepass(
    const float* __restrict__ x,
    const float* __restrict__ Wq, const float* __restrict__ Wk,
    const float* __restrict__ Wv, const float* __restrict__ Wp,
    __half* __restrict__ xh, __half* __restrict__ wcat,
    __half* __restrict__ wpt)
{
    const int z = blockIdx.z;
    if (z == 4) {
        // x -> half: 1024 blocks cover 4M floats (1M float4)
        const int base = (blockIdx.y * 32 + blockIdx.x) * 1024;  // float4 units
        #pragma unroll
        for (int i = 0; i < 4; i++) {
            const int idx = base + i * 256 + threadIdx.x;
            float4 v = ((const float4*)x)[idx];
            __half2 h0 = __floats2half2_rn(v.x, v.y);
            __half2 h1 = __floats2half2_rn(v.z, v.w);
            ((uint2*)xh)[idx] = make_uint2(*(uint32_t*)&h0, *(uint32_t*)&h1);
        }
        return;
    }

    __shared__ float t[32][33];
    const float* W = (z == 0) ? Wq : (z == 1) ? Wk : (z == 2) ? Wv : Wp;
    __half* Wt = (z < 3) ? (wcat + (size_t)z * C_ * C_) : wpt;

    const int tx = threadIdx.x & 31;
    const int ty = threadIdx.x >> 5;
    const int bx = blockIdx.x * 32;       // n block
    const int by = blockIdx.y * 32;       // k block
    #pragma unroll
    for (int i = ty; i < 32; i += 8)
        t[i][tx] = W[(size_t)(by + i) * C_ + bx + tx];
    __syncthreads();
    #pragma unroll
    for (int i = ty; i < 32; i += 8)
        Wt[(size_t)(bx + i) * C_ + by + tx] = __float2half(t[tx][i]);
}

// ----------------------------------------------------------------------------
// FP16 GEMM: 3-stage cp.async ring (one barrier per K-tile), software-
// pipelined ldmatrix fragment loads. D[m][n] = sum_k A[m][k]*Bt[n][k].
// MODE 1: N=3072, half out stride 3072, fused RoPE+RMSNorm on cols<2048.
// MODE 0: N=1024, fp32 out stride 1024.
// ----------------------------------------------------------------------------
#define GBM 128
#define GBN 128
#define GBK 64
#define GSTR 72
#define GNKT (C_/GBK)                         // 16
#define GSTAGE ((GBM + GBN) * GSTR)           // halfs per stage (18432)
#define GEMM_SMEM (3 * GSTAGE * 2)            // 110592 B

template<int MODE>
__global__ __launch_bounds__(256, 2) void gemm2(
    const __half* __restrict__ A, const __half* __restrict__ Bt, void* Co,
    const float* __restrict__ cosb, const float* __restrict__ sinb)
{
    extern __shared__ __half hsm[];
    constexpr int OSTR = MODE ? N3 : C_;

    const int tid  = threadIdx.x;
    const int lane = tid & 31;
    const int wid  = tid >> 5;
    const int wm   = wid >> 1;       // 0..3
    const int wn   = wid & 1;        // 0..1
    const int bm = blockIdx.y * GBM;
    const int bn = blockIdx.x * GBN;
    const int r  = lane >> 2;        // 0..7
    const int cq = lane & 3;         // 0..3

    const int lm_off = ((((lane >> 3) & 1) * 8 + (lane & 7)) * GSTR
                        + (lane >> 4) * 8) * 2;   // bytes

    float acc[2][8][4];
    #pragma unroll
    for (int mt = 0; mt < 2; mt++)
        #pragma unroll
        for (int nt = 0; nt < 8; nt++)
            #pragma unroll
            for (int i = 0; i < 4; i++) acc[mt][nt][i] = 0.0f;

    #define GH_PREFETCH(kt, st)                                                \
    {                                                                          \
        __half* As_ = hsm + (st) * GSTAGE;                                     \
        __half* Bs_ = As_ + GBM * GSTR;                                        \
        const __half* Ag = A  + (size_t)bm * C_ + (kt) * GBK;                  \
        const __half* Bg = Bt + (size_t)bn * C_ + (kt) * GBK;                  \
        _Pragma("unroll")                                                      \
        for (int it = 0; it < 4; it++) {                                       \
            const int idx = it * 256 + tid;                                    \
            const int row = idx >> 3, g = (idx & 7) * 8;                       \
            cpasync16(As_ + row * GSTR + g, Ag + (size_t)row * C_ + g);        \
        }                                                                      \
        _Pragma("unroll")                                                      \
        for (int it = 0; it < 4; it++) {                                       \
            const int idx = it * 256 + tid;                                    \
            const int row = idx >> 3, g = (idx & 7) * 8;                       \
            cpasync16(Bs_ + row * GSTR + g, Bg + (size_t)row * C_ + g);        \
        }                                                                      \
    }

    GH_PREFETCH(0, 0); CP_COMMIT();
    GH_PREFETCH(1, 1); CP_COMMIT();

    for (int kt = 0; kt < GNKT; kt++) {
        cp_wait<1>();          // tile kt landed (groups through g(kt) retired)
        __syncthreads();       // prior-iter readers of stage (kt+2)%3 done
        if (kt + 2 < GNKT) { GH_PREFETCH(kt + 2, (kt + 2) % 3); }
        CP_COMMIT();           // uniform group numbering

        const __half* As = hsm + (kt % 3) * GSTAGE;
        const __half* Bs = As + GBM * GSTR;
        const uint32_t as_u = (uint32_t)__cvta_generic_to_shared(As) + lm_off;
        const uint32_t bs_u = (uint32_t)__cvta_generic_to_shared(Bs) + lm_off;

        // Software-pipelined fragment loads: step s = kk*4 + ntp.
        uint32_t afb[2][2][4];   // [kk parity][mt][reg]
        uint32_t bfb[2][4];      // [s parity][reg] = {b0e, b0o, b1e, b1o}

        #define LOAD_A(kkx, buf)                                               \
            _Pragma("unroll")                                                  \
            for (int mt = 0; mt < 2; mt++)                                     \
                ldsm_x4(afb[buf][mt][0], afb[buf][mt][1],                      \
                        afb[buf][mt][2], afb[buf][mt][3],                      \
                        as_u + ((wm * 32 + mt * 16) * GSTR + (kkx) * 16) * 2);
        #define LOAD_B(kkx, ntpx, buf)                                         \
            ldsm_x4(bfb[buf][0], bfb[buf][1], bfb[buf][2], bfb[buf][3],        \
                    bs_u + ((wn * 64 + (ntpx) * 16) * GSTR + (kkx) * 16) * 2);

        LOAD_A(0, 0);
        LOAD_B(0, 0, 0);

        #pragma unroll
        for (int s = 0; s < 16; s++) {
            const int kk  = s >> 2, ntp = s & 3;
            const int cur = s & 1,  nxt = cur ^ 1;
            if (s < 15) {
                const int s1 = s + 1;
                const int kk1 = s1 >> 2, ntp1 = s1 & 3;
                LOAD_B(kk1, ntp1, nxt);
                if (ntp == 3) { LOAD_A(kk1, kk1 & 1); }
            }
            const int ap = kk & 1;
            mma_f16(acc[0][2*ntp],     afb[ap][0], bfb[cur][0], bfb[cur][2]);
            mma_f16(acc[0][2*ntp + 1], afb[ap][0], bfb[cur][1], bfb[cur][3]);
            mma_f16(acc[1][2*ntp],     afb[ap][1], bfb[cur][0], bfb[cur][2]);
            mma_f16(acc[1][2*ntp + 1], afb[ap][1], bfb[cur][1], bfb[cur][3]);
        }
        #undef LOAD_A
        #undef LOAD_B
    }

    // ---- Epilogue ----
    if (MODE == 0) {
        float* o = (float*)Co;
        #pragma unroll
        for (int mt = 0; mt < 2; mt++) {
            const int row = bm + wm * 32 + mt * 16 + r;
            #pragma unroll
            for (int nt = 0; nt < 8; nt++) {
                const int col = bn + wn * 64 + nt * 8 + cq * 2;
                *(float2*)(o + (size_t)row * OSTR + col) =
                    make_float2(acc[mt][nt][0], acc[mt][nt][1]);
                *(float2*)(o + (size_t)(row + 8) * OSTR + col) =
                    make_float2(acc[mt][nt][2], acc[mt][nt][3]);
            }
        }
    } else {
        // Fused RoPE + RMSNorm for q/k cols (<2048); v passes through.
        __half* o = (__half*)Co;
        const bool is_v = (bn + wn * 64) >= 2048;
        #pragma unroll
        for (int mt = 0; mt < 2; mt++) {
            #pragma unroll
            for (int rh = 0; rh < 2; rh++) {      // c0,c1 = row r; c2,c3 = r+8
                const int row = bm + wm * 32 + mt * 16 + r + rh * 8;
                const int i0 = rh * 2, i1 = rh * 2 + 1;
                float ov[8][2];
                if (!is_v) {
                    const int t = row & (T_ - 1);
                    float ssum = 0.0f;
                    #pragma unroll
                    for (int nt = 0; nt < 4; nt++) {
                        const int d0 = nt * 8 + cq * 2;
                        const float2 cc = *(const float2*)&cosb[(size_t)t * D_ + d0];
                        const float2 sn = *(const float2*)&sinb[(size_t)t * D_ + d0];
                        const float x1a = acc[mt][nt][i0],     x1b = acc[mt][nt][i1];
                        const float x2a = acc[mt][nt + 4][i0], x2b = acc[mt][nt + 4][i1];
                        ov[nt][0]     = x1a * cc.x - x2a * sn.x;
                        ov[nt][1]     = x1b * cc.y - x2b * sn.y;
                        ov[nt + 4][0] = x1a * sn.x + x2a * cc.x;
                        ov[nt + 4][1] = x1b * sn.y + x2b * cc.y;
                        ssum += ov[nt][0]*ov[nt][0] + ov[nt][1]*ov[nt][1]
                              + ov[nt+4][0]*ov[nt+4][0] + ov[nt+4][1]*ov[nt+4][1];
                    }
                    ssum += __shfl_xor_sync(0xffffffffu, ssum, 1);
                    ssum += __shfl_xor_sync(0xffffffffu, ssum, 2);
                    const float rinv = rsqrtf(ssum * (1.0f / 64.0f) + 1e-6f);
                    #pragma unroll
                    for (int nt = 0; nt < 8; nt++) {
                        ov[nt][0] *= rinv; ov[nt][1] *= rinv;
                    }
                } else {
                    #pragma unroll
                    for (int nt = 0; nt < 8; nt++) {
                        ov[nt][0] = acc[mt][nt][i0];
                        ov[nt][1] = acc[mt][nt][i1];
                    }
                }
                #pragma unroll
                for (int nt = 0; nt < 8; nt++) {
                    const int col = bn + wn * 64 + nt * 8 + cq * 2;
                    __half2 hv = __floats2half2_rn(ov[nt][0], ov[nt][1]);
                    *(uint32_t*)(o + (size_t)row * OSTR + col) = *(uint32_t*)&hv;
                }
            }
        }
    }
}

// ----------------------------------------------------------------------------
// Flash attention (round-10 version, verbatim): fixed-base softmax,
// register-resident P, 3-stage KV ring, one barrier per tile.
// ----------------------------------------------------------------------------
#define FSTRH 72
#define KVSTG (64 * FSTRH)                       // halfs per tensor per stage
#define FLASH_SMEM ((128*FSTRH + 3*2*KVSTG) * 2) // 73728 B
#define SOFTMAX_SCALE 0.180336880f               // 0.125 * log2(e)

__global__ __launch_bounds__(256) void flash_h(
    const __half* __restrict__ QKV, __half* __restrict__ O)
{
    extern __shared__ __half fsm[];
    __half* Pb = fsm;                            // [128][72] (Q staging only)
    const uint32_t pb_u = (uint32_t)__cvta_generic_to_shared(Pb);

    const int tid  = threadIdx.x;
    const int lane = tid & 31;
    const int warp = tid >> 5;         // 0..7
    const int r  = lane >> 2;          // 0..7
    const int cq = lane & 3;           // 0..3
    const int b = blockIdx.z, h = blockIdx.y;
    const int qi = (int)(gridDim.x - 1 - blockIdx.x);   // heavy blocks first
    const int q0 = qi * 128;
    const int m0 = warp * 16;

    const size_t rowstride = N3;           // 3072 halfs

    const int lm_off = ((((lane >> 3) & 1) * 8 + (lane & 7)) * FSTRH
                        + (lane >> 4) * 8) * 2;   // bytes (A/B-type ldmatrix)

    // trans-ldmatrix (V) per-lane decomposition
    const int lm_rr  = lane & 7;
    const int lm_sel = lane >> 3;
    const int lm_kad = ((lm_sel & 1) << 3) + lm_rr;
    const int lm_dad = (lm_sel >> 1) << 3;

    const __half* kbase = QKV + (size_t)(b * T_) * rowstride + C_   + h * D_;
    const __half* vbase = QKV + (size_t)(b * T_) * rowstride + 2*C_ + h * D_;

    #define KV_STAGE_K(s) (fsm + 128 * FSTRH + (s) * 2 * KVSTG)
    #define KV_STAGE_V(s) (KV_STAGE_K(s) + KVSTG)

    #define KVH_PREFETCH(jt, s)                                                \
    {                                                                          \
        __half* Kbuf = KV_STAGE_K(s);                                          \
        __half* Vbuf = KV_STAGE_V(s);                                          \
        _Pragma("unroll")                                                      \
        for (int it = 0; it < 2; it++) {                                       \
            const int idx = it * 256 + tid;                                    \
            const int row = idx >> 3;                                          \
            const int g   = (idx & 7) * 8;                                     \
            const __half* kg = kbase + (size_t)((jt) * 64 + row) * rowstride;  \
            const __half* vg = vbase + (size_t)((jt) * 64 + row) * rowstride;  \
            cpasync16(Kbuf + row * FSTRH + g, kg + g);                         \
            cpasync16(Vbuf + row * FSTRH + g, vg + g);                         \
        }                                                                      \
    }

    const int ntile = 2 * qi + 2;

    // ---- Stage Q into Pb (plain stores); prefetch K/V tiles 0,1 ----
    const __half* qb = QKV + (size_t)(b * T_ + q0) * rowstride + h * D_;
    #pragma unroll
    for (int it = 0; it < 4; it++) {
        const int idx = it * 256 + tid;
        const int row = idx >> 3;
        const int g   = (idx & 7) * 8;
        *(uint4*)&Pb[row * FSTRH + g] =
            *(const uint4*)(qb + (size_t)row * rowstride + g);
    }
    KVH_PREFETCH(0, 0); CP_COMMIT();
    if (ntile > 1) { KVH_PREFETCH(1, 1); }
    CP_COMMIT();
    __syncthreads();          // Q visible

    uint32_t qa[4][4];
    #pragma unroll
    for (int kk = 0; kk < 4; kk++)
        ldsm_x4(qa[kk][0], qa[kk][1], qa[kk][2], qa[kk][3],
                pb_u + (m0 * FSTRH + kk * 16) * 2 + lm_off);

    float l_lo = 0.0f, l_hi = 0.0f;
    float oacc[8][4];
    #pragma unroll
    for (int dt = 0; dt < 8; dt++)
        #pragma unroll
        for (int i = 0; i < 4; i++) oacc[dt][i] = 0.0f;

    for (int jt = 0; jt < ntile; jt++) {
        cp_wait<1>();          // stage jt data landed (groups: jt done)
        __syncthreads();       // all copies visible; readers of stage (jt+2)%3 done
        if (jt + 2 < ntile) { KVH_PREFETCH(jt + 2, (jt + 2) % 3); }
        CP_COMMIT();           // keep group numbering uniform

        const __half* Ks = KV_STAGE_K(jt % 3);
        const __half* Vs = KV_STAGE_V(jt % 3);
        const uint32_t ks_u = (uint32_t)__cvta_generic_to_shared(Ks) + lm_off;
        const uint32_t vs_u = (uint32_t)__cvta_generic_to_shared(Vs);
        const int k0 = jt * 64;

        // ---- S = Q @ K^T ----
        float sacc[8][4];
        #pragma unroll
        for (int nt = 0; nt < 8; nt++)
            #pragma unroll
            for (int i = 0; i < 4; i++) sacc[nt][i] = 0.0f;

        #pragma unroll
        for (int kk = 0; kk < 4; kk++) {
            const int kb2 = kk * 16;
            #pragma unroll
            for (int ntp = 0; ntp < 4; ntp++) {
                uint32_t b0e, b0o, b1e, b1o;
                ldsm_x4(b0e, b0o, b1e, b1o,
                        ks_u + (ntp * 16 * FSTRH + kb2) * 2);
                mma_f16(sacc[2*ntp],     qa[kk], b0e, b1e);
                mma_f16(sacc[2*ntp + 1], qa[kk], b0o, b1o);
            }
        }

        // ---- mask (diagonal tiles only) + exp2(s * scale) ----
        if (jt >= 2 * qi) {
            const int row_lo = q0 + m0 + r;
            const int row_hi = row_lo + 8;
            #pragma unroll
            for (int nt = 0; nt < 8; nt++) {
                const int c0 = k0 + nt * 8 + cq * 2;
                if (row_lo < c0    ) sacc[nt][0] = -1e30f;
                if (row_lo < c0 + 1) sacc[nt][1] = -1e30f;
                if (row_hi < c0    ) sacc[nt][2] = -1e30f;
                if (row_hi < c0 + 1) sacc[nt][3] = -1e30f;
            }
        }
        #pragma unroll
        for (int nt = 0; nt < 8; nt++) {
            sacc[nt][0] = ex2f(sacc[nt][0] * SOFTMAX_SCALE);
            sacc[nt][1] = ex2f(sacc[nt][1] * SOFTMAX_SCALE);
            sacc[nt][2] = ex2f(sacc[nt][2] * SOFTMAX_SCALE);
            sacc[nt][3] = ex2f(sacc[nt][3] * SOFTMAX_SCALE);
            l_lo += sacc[nt][0] + sacc[nt][1];
            l_hi += sacc[nt][2] + sacc[nt][3];
        }

        // ---- O += P @ V (P straight from registers; C-frag == A-frag) ----
        #pragma unroll
        for (int kk = 0; kk < 4; kk++) {
            uint32_t pa[4];
            pa[0] = packh2(sacc[2*kk][0],     sacc[2*kk][1]);
            pa[1] = packh2(sacc[2*kk][2],     sacc[2*kk][3]);
            pa[2] = packh2(sacc[2*kk + 1][0], sacc[2*kk + 1][1]);
            pa[3] = packh2(sacc[2*kk + 1][2], sacc[2*kk + 1][3]);
            const int kb2 = kk * 16;
            #pragma unroll
            for (int dtp = 0; dtp < 4; dtp++) {
                uint32_t v0, v1, v2, v3;
                const uint32_t addr = vs_u +
                    (uint32_t)(((kb2 + lm_kad) * FSTRH + dtp * 16 + lm_dad) * 2);
                ldsm_x4_t(v0, v1, v2, v3, addr);
                mma_f16(oacc[2*dtp],     pa, v0, v1);
                mma_f16(oacc[2*dtp + 1], pa, v2, v3);
            }
        }
    }

    // ---- final l reduction across cq group, normalize + store ----
    l_lo += __shfl_xor_sync(0xffffffffu, l_lo, 1);
    l_lo += __shfl_xor_sync(0xffffffffu, l_lo, 2);
    l_hi += __shfl_xor_sync(0xffffffffu, l_hi, 1);
    l_hi += __shfl_xor_sync(0xffffffffu, l_hi, 2);
    const float inv_lo = 1.0f / l_lo;
    const float inv_hi = 1.0f / l_hi;

    __half* ob = O + ((size_t)(b * T_ + q0) * H_ + h) * D_;
    #pragma unroll
    for (int dt = 0; dt < 8; dt++) {
        const int cc = dt * 8 + cq * 2;
        const uint32_t h0 = packh2(oacc[dt][0] * inv_lo, oacc[dt][1] * inv_lo);
        const uint32_t h1 = packh2(oacc[dt][2] * inv_hi, oacc[dt][3] * inv_hi);
        *(uint32_t*)(ob + (size_t)(m0 + r) * C_ + cc)     = h0;
        *(uint32_t*)(ob + (size_t)(m0 + r + 8) * C_ + cc) = h1;
    }
}

// ----------------------------------------------------------------------------
// Launch
// ----------------------------------------------------------------------------
extern "C" void kernel_launch(void* const* d_in, const int* in_sizes, int n_in,
                              void* d_out, int out_size)
{
    const float* x    = (const float*)d_in[0];
    const float* cosb = (const float*)d_in[1];
    const float* sinb = (const float*)d_in[2];
    const float* Wq   = (const float*)d_in[3];
    const float* Wk   = (const float*)d_in[4];
    const float* Wv   = (const float*)d_in[5];
    const float* Wp   = (const float*)d_in[6];
    float* out = (float*)d_out;

    __half *xh, *qkv, *yh, *wcat, *wpt;
    cudaGetSymbolAddress((void**)&xh,   g_xh);
    cudaGetSymbolAddress((void**)&qkv,  g_qkv);
    cudaGetSymbolAddress((void**)&yh,   g_yh);
    cudaGetSymbolAddress((void**)&wcat, g_wcat);
    cudaGetSymbolAddress((void**)&wpt,  g_wpt);

    cudaFuncSetAttribute(gemm2<1>,
        cudaFuncAttributeMaxDynamicSharedMemorySize, GEMM_SMEM);
    cudaFuncSetAttribute(gemm2<0>,
        cudaFuncAttributeMaxDynamicSharedMemorySize, GEMM_SMEM);
    cudaFuncSetAttribute(flash_h,
        cudaFuncAttributeMaxDynamicSharedMemorySize, FLASH_SMEM);

    // Fused pre-pass: W transposes (z=0..3) + x conversion (z=4)
    dim3 pgrid0(C_ / 32, C_ / 32, 5);
    prepass<<<pgrid0, 256>>>(x, Wq, Wk, Wv, Wp, xh, wcat, wpt);

    // Fused QKV projection + RoPE + RMSNorm
    dim3 qgrid(N3 / GBN, M_ / GBM);   // (24, 32)
    gemm2<1><<<qgrid, 256, GEMM_SMEM>>>(xh, wcat, qkv, cosb, sinb);

    // Attention
    dim3 fgrid(T_ / 128, H_, B_);     // (16, 16, 2)
    flash_h<<<fgrid, 256, FLASH_SMEM>>>(qkv, yh);

    // Output projection (fp32 out)
    dim3 pgrid(C_ / GBN, M_ / GBM);   // (8, 32)
    gemm2<0><<<pgrid, 256, GEMM_SMEM>>>(yh, wpt, out, cosb, sinb);
}